// round 7
// baseline (speedup 1.0000x reference)
#include <cuda_runtime.h>
#include <math.h>
#include <stdint.h>

// Problem constants (B=2, N=4096, C=256, K=64; hidden = 256, out = 256)
#define PB 2
#define PN 4096
#define PC 256
#define PK 64
#define THREADS 1024
#define NSL 32              // gather slices: 1024 threads / 32 quads

__device__ __forceinline__ uint32_t smem_u32(const void* p) {
    uint32_t a;
    asm("{ .reg .u64 t; cvta.to.shared.u64 t, %1; cvt.u32.u64 %0, t; }" : "=r"(a) : "l"(p));
    return a;
}
__device__ __forceinline__ uint32_t mapa_rank(uint32_t addr, uint32_t rank) {
    uint32_t r;
    asm("mapa.shared::cluster.u32 %0, %1, %2;" : "=r"(r) : "r"(addr), "r"(rank));
    return r;
}
__device__ __forceinline__ void st_cluster_f32(uint32_t addr, float v) {
    asm volatile("st.shared::cluster.f32 [%0], %1;" :: "r"(addr), "f"(v) : "memory");
}
__device__ __forceinline__ void cluster_sync_all() {
    asm volatile("barrier.cluster.arrive.aligned;" ::: "memory");
    asm volatile("barrier.cluster.wait.aligned;" ::: "memory");
}

__global__ __launch_bounds__(THREADS, 2) __cluster_dims__(2, 1, 1)
void roi_fused_kernel(const float* __restrict__ points,        // (B, N, 3)
                      const float* __restrict__ feats,         // (B, N, C)
                      const float* __restrict__ props,         // (B, K, 7)
                      const float* __restrict__ W1,            // (C, 256)
                      const float* __restrict__ b1,            // (256)
                      const float* __restrict__ W2,            // (256, 256)
                      const float* __restrict__ b2,            // (256)
                      float* __restrict__ out)                 // (B, K, 256)
{
    const int bk = blockIdx.x >> 1;     // 0 .. B*K-1
    const int b  = bk / PK;
    const int t  = threadIdx.x;
    uint32_t rank;
    asm("mov.u32 %0, %%cluster_ctarank;" : "=r"(rank));   // 0 or 1 (channel half)

    const int qq  = t & 31;             // quad within my 128-channel half
    const int sl  = t >> 5;             // slice 0..31

    __shared__ int    s_idx[PN];
    __shared__ int    s_count;
    __shared__ float  s_box[6];
    __shared__ float4 s_part[THREADS];  // 16 KB reduction scratch
    __shared__ float4 s_vec[64];        // FULL pooled vector (both halves)
    __shared__ float4 s_h[64];          // FULL hidden vector (both halves)

    if (t == 0) s_count = 0;
    if (t < 3) {
        float c = props[bk * 7 + t];
        float h = props[bk * 7 + 3 + t] * 0.5f;
        s_box[t]     = c - h;   // lo
        s_box[t + 3] = c + h;   // hi
    }
    __syncthreads();

    const float lx = s_box[0], ly = s_box[1], lz = s_box[2];
    const float hx = s_box[3], hy = s_box[4], hz = s_box[5];

    // ---- Phase 1: compact inside-point indices (both CTAs do it redundantly) ----
    const float* pb = points + (size_t)b * PN * 3;
    #pragma unroll
    for (int it = 0; it < PN / THREADS; it++) {
        int n = it * THREADS + t;
        float px = pb[n * 3 + 0];
        float py = pb[n * 3 + 1];
        float pz = pb[n * 3 + 2];
        bool inside = (px > lx) & (px < hx) &
                      (py > ly) & (py < hy) &
                      (pz > lz) & (pz < hz);
        if (inside) {
            int pos = atomicAdd(&s_count, 1);
            s_idx[pos] = n;
        }
    }
    __syncthreads();
    const int cnt = s_count;

    // ---- Phase 2: max-pool MY 128 channels; 32 slices stride the list ----
    // feats row quad base for my half: rank*32
    const float4* fb4 = (const float4*)(feats + (size_t)b * PN * PC);
    const int colq = rank * 32 + qq;
    float4 acc = make_float4(-INFINITY, -INFINITY, -INFINITY, -INFINITY);
    {
        int i = sl;
        for (; i + 3 * NSL < cnt; i += 4 * NSL) {
            int n0 = s_idx[i + 0 * NSL];
            int n1 = s_idx[i + 1 * NSL];
            int n2 = s_idx[i + 2 * NSL];
            int n3 = s_idx[i + 3 * NSL];
            float4 v0 = fb4[(size_t)n0 * 64 + colq];
            float4 v1 = fb4[(size_t)n1 * 64 + colq];
            float4 v2 = fb4[(size_t)n2 * 64 + colq];
            float4 v3 = fb4[(size_t)n3 * 64 + colq];
            acc.x = fmaxf(acc.x, fmaxf(fmaxf(v0.x, v1.x), fmaxf(v2.x, v3.x)));
            acc.y = fmaxf(acc.y, fmaxf(fmaxf(v0.y, v1.y), fmaxf(v2.y, v3.y)));
            acc.z = fmaxf(acc.z, fmaxf(fmaxf(v0.z, v1.z), fmaxf(v2.z, v3.z)));
            acc.w = fmaxf(acc.w, fmaxf(fmaxf(v0.w, v1.w), fmaxf(v2.w, v3.w)));
        }
        for (; i < cnt; i += NSL) {
            float4 v = fb4[(size_t)s_idx[i] * 64 + colq];
            acc.x = fmaxf(acc.x, v.x);
            acc.y = fmaxf(acc.y, v.y);
            acc.z = fmaxf(acc.z, v.z);
            acc.w = fmaxf(acc.w, v.w);
        }
    }
    s_part[t] = acc;
    __syncthreads();

    // reduce 32 slices -> 1 (t<32 owns quad t of my half), publish to self + peer
    if (t < 32) {
        float4 a = s_part[t];
        #pragma unroll
        for (int g = 1; g < NSL; g++) {
            float4 c = s_part[g * 32 + t];
            a.x = fmaxf(a.x, c.x);
            a.y = fmaxf(a.y, c.y);
            a.z = fmaxf(a.z, c.z);
            a.w = fmaxf(a.w, c.w);
        }
        if (cnt == 0) a = make_float4(0.f, 0.f, 0.f, 0.f);
        int vq = rank * 32 + t;         // global quad index of my result
        s_vec[vq] = a;
        uint32_t peer = mapa_rank(smem_u32(&s_vec[vq]), rank ^ 1u);
        st_cluster_f32(peer +  0, a.x);
        st_cluster_f32(peer +  4, a.y);
        st_cluster_f32(peer +  8, a.z);
        st_cluster_f32(peer + 12, a.w);
    }
    cluster_sync_all();                 // full pooled vector visible in both CTAs

    // ---- Phase 3: h-half = relu(pooled @ W1 + b1); slice covers 8 c's ----
    {
        const float4* W1_4 = (const float4*)W1;
        const float*  vecf = (const float*)s_vec;
        float4 ha = make_float4(0.f, 0.f, 0.f, 0.f);
        const int c0 = sl * 8;
        #pragma unroll
        for (int c = 0; c < 8; c++) {
            float f = vecf[c0 + c];                  // warp-uniform broadcast
            float4 w = W1_4[(size_t)(c0 + c) * 64 + colq];
            ha.x = fmaf(f, w.x, ha.x);
            ha.y = fmaf(f, w.y, ha.y);
            ha.z = fmaf(f, w.z, ha.z);
            ha.w = fmaf(f, w.w, ha.w);
        }
        s_part[t] = ha;
    }
    __syncthreads();
    if (t < 32) {
        float4 a = s_part[t];
        #pragma unroll
        for (int g = 1; g < NSL; g++) {
            float4 c = s_part[g * 32 + t];
            a.x += c.x; a.y += c.y; a.z += c.z; a.w += c.w;
        }
        int vq = rank * 32 + t;
        float4 bb = ((const float4*)b1)[vq];
        a.x = fmaxf(a.x + bb.x, 0.f);
        a.y = fmaxf(a.y + bb.y, 0.f);
        a.z = fmaxf(a.z + bb.z, 0.f);
        a.w = fmaxf(a.w + bb.w, 0.f);
        s_h[vq] = a;
        uint32_t peer = mapa_rank(smem_u32(&s_h[vq]), rank ^ 1u);
        st_cluster_f32(peer +  0, a.x);
        st_cluster_f32(peer +  4, a.y);
        st_cluster_f32(peer +  8, a.z);
        st_cluster_f32(peer + 12, a.w);
    }
    cluster_sync_all();                 // full hidden vector visible in both CTAs

    // ---- Phase 4: out-half = relu(h @ W2 + b2) ----
    {
        const float4* W2_4 = (const float4*)W2;
        const float*  hf = (const float*)s_h;
        float4 oa = make_float4(0.f, 0.f, 0.f, 0.f);
        const int c0 = sl * 8;
        #pragma unroll
        for (int c = 0; c < 8; c++) {
            float f = hf[c0 + c];
            float4 w = W2_4[(size_t)(c0 + c) * 64 + colq];
            oa.x = fmaf(f, w.x, oa.x);
            oa.y = fmaf(f, w.y, oa.y);
            oa.z = fmaf(f, w.z, oa.z);
            oa.w = fmaf(f, w.w, oa.w);
        }
        s_part[t] = oa;
    }
    __syncthreads();
    if (t < 32) {
        float4 a = s_part[t];
        #pragma unroll
        for (int g = 1; g < NSL; g++) {
            float4 c = s_part[g * 32 + t];
            a.x += c.x; a.y += c.y; a.z += c.z; a.w += c.w;
        }
        int vq = rank * 32 + t;
        float4 bb = ((const float4*)b2)[vq];
        a.x = fmaxf(a.x + bb.x, 0.f);
        a.y = fmaxf(a.y + bb.y, 0.f);
        a.z = fmaxf(a.z + bb.z, 0.f);
        a.w = fmaxf(a.w + bb.w, 0.f);
        ((float4*)out)[(size_t)bk * 64 + vq] = a;
    }
    // no CTA may exit while peer stores into its SMEM could be in flight
    cluster_sync_all();
}

extern "C" void kernel_launch(void* const* d_in, const int* in_sizes, int n_in,
                              void* d_out, int out_size)
{
    const float* points = (const float*)d_in[0];   // (B, N, 3)
    const float* feats  = (const float*)d_in[1];   // (B, N, C)
    const float* props  = (const float*)d_in[2];   // (B, K, 7)
    const float* W1     = (const float*)d_in[3];   // (C, 256)
    const float* b1     = (const float*)d_in[4];   // (256)
    const float* W2     = (const float*)d_in[5];   // (256, 256)
    const float* b2     = (const float*)d_in[6];   // (256)
    float*       out    = (float*)d_out;           // (B, K, 256)

    roi_fused_kernel<<<PB * PK * 2, THREADS>>>(points, feats, props, W1, b1, W2, b2, out);
}

// round 8
// speedup vs baseline: 1.2850x; 1.2850x over previous
#include <cuda_runtime.h>
#include <math.h>

// Problem constants (B=2, N=4096, C=256, K=64; hidden = 256, out = 256)
#define PB 2
#define PN 4096
#define PC 256
#define PK 64
#define NS 8                 // split-K over points: 8 segments of 512 points
#define SEG (PN / NS)        // 512 points per segment

// Scratch: partial maxima [B*K][NS][64 float4] and counts [B*K][NS]
__device__ float4 g_part4[PB * PK * NS * 64];
__device__ int    g_cnt[PB * PK * NS];

// ---------------- Kernel A: segment pooling ----------------
__global__ __launch_bounds__(256)
void pool_partial_kernel(const float* __restrict__ points,   // (B, N, 3)
                         const float* __restrict__ feats,    // (B, N, C)
                         const float* __restrict__ props)    // (B, K, 7)
{
    const int blk = blockIdx.x;      // bk * NS + s
    const int bk  = blk >> 3;
    const int s   = blk & (NS - 1);
    const int b   = bk / PK;
    const int t   = threadIdx.x;
    const int q   = t & 63;          // channel quad
    const int sl  = t >> 6;          // slice 0..3

    __shared__ int    s_idx[SEG];
    __shared__ int    s_count;
    __shared__ float  s_box[6];
    __shared__ float4 s_part[256];

    if (t == 0) s_count = 0;
    if (t < 3) {
        float c = props[bk * 7 + t];
        float h = props[bk * 7 + 3 + t] * 0.5f;
        s_box[t]     = c - h;
        s_box[t + 3] = c + h;
    }
    __syncthreads();

    const float lx = s_box[0], ly = s_box[1], lz = s_box[2];
    const float hx = s_box[3], hy = s_box[4], hz = s_box[5];

    // test my 512-point segment
    const float* pb = points + (size_t)b * PN * 3;
    const int n0 = s * SEG;
    #pragma unroll
    for (int it = 0; it < SEG / 256; it++) {
        int n = n0 + it * 256 + t;
        float px = pb[n * 3 + 0];
        float py = pb[n * 3 + 1];
        float pz = pb[n * 3 + 2];
        bool inside = (px > lx) & (px < hx) &
                      (py > ly) & (py < hy) &
                      (pz > lz) & (pz < hz);
        if (inside) {
            int pos = atomicAdd(&s_count, 1);
            s_idx[pos] = n;
        }
    }
    __syncthreads();
    const int cnt = s_count;

    // max-pool my subset; 4 slices stride the list; float4 lanes
    const float4* fb4 = (const float4*)(feats + (size_t)b * PN * PC);
    float4 acc = make_float4(-INFINITY, -INFINITY, -INFINITY, -INFINITY);
    {
        int i = sl;
        for (; i + 3 * 4 < cnt; i += 16) {
            int i0 = s_idx[i + 0];
            int i1 = s_idx[i + 4];
            int i2 = s_idx[i + 8];
            int i3 = s_idx[i + 12];
            float4 v0 = fb4[(size_t)i0 * 64 + q];
            float4 v1 = fb4[(size_t)i1 * 64 + q];
            float4 v2 = fb4[(size_t)i2 * 64 + q];
            float4 v3 = fb4[(size_t)i3 * 64 + q];
            acc.x = fmaxf(acc.x, fmaxf(fmaxf(v0.x, v1.x), fmaxf(v2.x, v3.x)));
            acc.y = fmaxf(acc.y, fmaxf(fmaxf(v0.y, v1.y), fmaxf(v2.y, v3.y)));
            acc.z = fmaxf(acc.z, fmaxf(fmaxf(v0.z, v1.z), fmaxf(v2.z, v3.z)));
            acc.w = fmaxf(acc.w, fmaxf(fmaxf(v0.w, v1.w), fmaxf(v2.w, v3.w)));
        }
        for (; i < cnt; i += 4) {
            float4 v = fb4[(size_t)s_idx[i] * 64 + q];
            acc.x = fmaxf(acc.x, v.x);
            acc.y = fmaxf(acc.y, v.y);
            acc.z = fmaxf(acc.z, v.z);
            acc.w = fmaxf(acc.w, v.w);
        }
    }
    s_part[t] = acc;
    __syncthreads();

    if (t < 64) {
        float4 a  = s_part[t];
        float4 c1 = s_part[64 + t];
        float4 c2 = s_part[128 + t];
        float4 c3 = s_part[192 + t];
        a.x = fmaxf(fmaxf(a.x, c1.x), fmaxf(c2.x, c3.x));
        a.y = fmaxf(fmaxf(a.y, c1.y), fmaxf(c2.y, c3.y));
        a.z = fmaxf(fmaxf(a.z, c1.z), fmaxf(c2.z, c3.z));
        a.w = fmaxf(fmaxf(a.w, c1.w), fmaxf(c2.w, c3.w));
        g_part4[(size_t)blk * 64 + t] = a;   // may be -inf if slice empty
    }
    if (t == 0) g_cnt[blk] = cnt;
}

// ---------------- Kernel B: reduce partials + MLP ----------------
#define THREADS 1024
#define NSL 16

__global__ __launch_bounds__(THREADS)
void mlp_kernel(const float* __restrict__ W1,   // (C, 256)
                const float* __restrict__ b1,
                const float* __restrict__ W2,   // (256, 256)
                const float* __restrict__ b2,
                float* __restrict__ out)        // (B, K, 256)
{
    const int bk = blockIdx.x;
    const int t  = threadIdx.x;
    const int q  = t & 63;
    const int sl = t >> 6;

    __shared__ float4 s_part[THREADS];   // 16 KB scratch (also holds loaded partials)
    __shared__ float4 s_vec[64];
    __shared__ float4 s_h[64];
    __shared__ int    s_cnt;

    // load the 8 partial vectors (contiguous 512 float4) coalesced
    if (t < NS * 64) {
        s_part[t] = g_part4[(size_t)bk * (NS * 64) + t];
    }
    if (t == 0) {
        int c = 0;
        #pragma unroll
        for (int i = 0; i < NS; i++) c += g_cnt[bk * NS + i];
        s_cnt = c;
    }
    __syncthreads();

    if (t < 64) {
        float4 a = s_part[t];
        #pragma unroll
        for (int g = 1; g < NS; g++) {
            float4 c = s_part[g * 64 + t];
            a.x = fmaxf(a.x, c.x);
            a.y = fmaxf(a.y, c.y);
            a.z = fmaxf(a.z, c.z);
            a.w = fmaxf(a.w, c.w);
        }
        if (s_cnt == 0) a = make_float4(0.f, 0.f, 0.f, 0.f);
        s_vec[t] = a;
    }
    __syncthreads();

    // ---- layer 1: h = relu(pooled @ W1 + b1); slice sl covers 16 c's ----
    {
        const float4* W1_4 = (const float4*)W1;
        const float*  vecf = (const float*)s_vec;
        float4 ha = make_float4(0.f, 0.f, 0.f, 0.f);
        const int c0 = sl * 16;
        #pragma unroll
        for (int c = 0; c < 16; c++) {
            float f = vecf[c0 + c];                  // warp-uniform broadcast
            float4 w = W1_4[(size_t)(c0 + c) * 64 + q];
            ha.x = fmaf(f, w.x, ha.x);
            ha.y = fmaf(f, w.y, ha.y);
            ha.z = fmaf(f, w.z, ha.z);
            ha.w = fmaf(f, w.w, ha.w);
        }
        s_part[t] = ha;
    }
    __syncthreads();
    if (t < 64) {
        float4 a = s_part[t];
        #pragma unroll
        for (int g = 1; g < NSL; g++) {
            float4 c = s_part[g * 64 + t];
            a.x += c.x; a.y += c.y; a.z += c.z; a.w += c.w;
        }
        float4 bb = ((const float4*)b1)[t];
        a.x = fmaxf(a.x + bb.x, 0.f);
        a.y = fmaxf(a.y + bb.y, 0.f);
        a.z = fmaxf(a.z + bb.z, 0.f);
        a.w = fmaxf(a.w + bb.w, 0.f);
        s_h[t] = a;
    }
    __syncthreads();

    // ---- layer 2: out = relu(h @ W2 + b2) ----
    {
        const float4* W2_4 = (const float4*)W2;
        const float*  hf = (const float*)s_h;
        float4 oa = make_float4(0.f, 0.f, 0.f, 0.f);
        const int c0 = sl * 16;
        #pragma unroll
        for (int c = 0; c < 16; c++) {
            float f = hf[c0 + c];
            float4 w = W2_4[(size_t)(c0 + c) * 64 + q];
            oa.x = fmaf(f, w.x, oa.x);
            oa.y = fmaf(f, w.y, oa.y);
            oa.z = fmaf(f, w.z, oa.z);
            oa.w = fmaf(f, w.w, oa.w);
        }
        s_part[t] = oa;
    }
    __syncthreads();
    if (t < 64) {
        float4 a = s_part[t];
        #pragma unroll
        for (int g = 1; g < NSL; g++) {
            float4 c = s_part[g * 64 + t];
            a.x += c.x; a.y += c.y; a.z += c.z; a.w += c.w;
        }
        float4 bb = ((const float4*)b2)[t];
        a.x = fmaxf(a.x + bb.x, 0.f);
        a.y = fmaxf(a.y + bb.y, 0.f);
        a.z = fmaxf(a.z + bb.z, 0.f);
        a.w = fmaxf(a.w + bb.w, 0.f);
        ((float4*)out)[(size_t)bk * 64 + t] = a;
    }
}

extern "C" void kernel_launch(void* const* d_in, const int* in_sizes, int n_in,
                              void* d_out, int out_size)
{
    const float* points = (const float*)d_in[0];   // (B, N, 3)
    const float* feats  = (const float*)d_in[1];   // (B, N, C)
    const float* props  = (const float*)d_in[2];   // (B, K, 7)
    const float* W1     = (const float*)d_in[3];   // (C, 256)
    const float* b1     = (const float*)d_in[4];   // (256)
    const float* W2     = (const float*)d_in[5];   // (256, 256)
    const float* b2     = (const float*)d_in[6];   // (256)
    float*       out    = (float*)d_out;           // (B, K, 256)

    pool_partial_kernel<<<PB * PK * NS, 256>>>(points, feats, props);
    mlp_kernel<<<PB * PK, THREADS>>>(W1, b1, W2, b2, out);
}